// round 4
// baseline (speedup 1.0000x reference)
#include <cuda_runtime.h>
#include <cuda_bf16.h>

#define B_ 4
#define H_ 224
#define W_ 224
#define C_ 64
#define K_ 8
#define EPS_ 1e-6f

#define H2_W 226            // s in [-1, 224], stored at idx s+1
#define H8_W 232            // s in [-7, 224], stored at idx s+7
#define ST2 (H2_W * C_)     // 14464
#define ST8 (H8_W * C_)     // 14848
#define STX (W_ * C_)       // 14336
#define CH_ 56              // rows per kB chunk (4 chunks)

__device__ float g_H2[(size_t)B_ * H_ * H2_W * C_];
__device__ float g_H8[(size_t)B_ * H_ * H8_W * C_];
__device__ float g_mn[B_], g_mx[B_];

static __device__ __forceinline__ void atomicMinF(float* a, float v) {
    if (v >= 0.f) atomicMin((int*)a, __float_as_int(v));
    else          atomicMax((unsigned int*)a, __float_as_uint(v));
}
static __device__ __forceinline__ void atomicMaxF(float* a, float v) {
    if (v >= 0.f) atomicMax((int*)a, __float_as_int(v));
    else          atomicMin((unsigned int*)a, __float_as_uint(v));
}

__global__ void k_init() {
    if (threadIdx.x < B_) {
        g_mn[threadIdx.x] = __int_as_float(0x7f800000);   // +inf
        g_mx[threadIdx.x] = __int_as_float(0xff800000);   // -inf
    }
}

__global__ void k_minmax(const float* __restrict__ x) {
    const int b = blockIdx.y;
    const float4* p = (const float4*)(x + (size_t)b * H_ * W_ * C_);
    const int n4 = H_ * W_ * C_ / 4;
    float mn = 3.402823466e38f, mx = -3.402823466e38f;
    for (int i = blockIdx.x * blockDim.x + threadIdx.x; i < n4; i += gridDim.x * blockDim.x) {
        float4 v = p[i];
        mn = fminf(mn, fminf(fminf(v.x, v.y), fminf(v.z, v.w)));
        mx = fmaxf(mx, fmaxf(fmaxf(v.x, v.y), fmaxf(v.z, v.w)));
    }
    #pragma unroll
    for (int o = 16; o; o >>= 1) {
        mn = fminf(mn, __shfl_xor_sync(0xffffffffu, mn, o));
        mx = fmaxf(mx, __shfl_xor_sync(0xffffffffu, mx, o));
    }
    __shared__ float smn[8], smx[8];
    int w = threadIdx.x >> 5, l = threadIdx.x & 31;
    if (l == 0) { smn[w] = mn; smx[w] = mx; }
    __syncthreads();
    if (threadIdx.x == 0) {
        int nw = blockDim.x >> 5;
        for (int i = 1; i < nw; i++) { mn = fminf(mn, smn[i]); mx = fmaxf(mx, smx[i]); }
        atomicMinF(&g_mn[b], mn);
        atomicMaxF(&g_mx[b], mx);
    }
}

// H2s(sa) = clipped sum of xs over cols [sa, sa+1], sa = s-1, s in [0,226)
__global__ void kA1(const float* __restrict__ x) {
    const int c = threadIdx.x;
    const int s = blockIdx.x * 4 + threadIdx.y;
    const int t = blockIdx.y, b = blockIdx.z;
    if (s >= H2_W) return;
    const float mn = g_mn[b];
    const float inv = 1.f / (g_mx[b] - mn + EPS_);
    const int sa = s - 1;
    const float* xr = x + (((size_t)b * H_ + t) * W_) * C_ + c;
    float sum = 0.f, n = 0.f;
    if (sa >= 0 && sa < W_)         { sum += xr[sa * C_];       n += 1.f; }
    if (sa + 1 >= 0 && sa + 1 < W_) { sum += xr[(sa + 1) * C_]; n += 1.f; }
    g_H2[(((size_t)b * H_ + t) * H2_W + s) * C_ + c] = (sum - n * mn) * inv;
}

// H8s(sa) = H2s(sa) + H2s(sa+2) + H2s(sa+4) + H2s(sa+6), sa = u-7, u in [0,232)
__global__ void kA2() {
    const int c = threadIdx.x;
    const int u = blockIdx.x * 4 + threadIdx.y;
    const int t = blockIdx.y, b = blockIdx.z;
    if (u >= H8_W) return;
    const int sa = u - 7;
    const float* h2 = g_H2 + (((size_t)b * H_ + t) * H2_W) * C_ + c;
    float sum = 0.f;
    #pragma unroll
    for (int d = 0; d < 8; d += 2) {
        int sp = sa + d;
        if (sp >= -1 && sp <= 224) sum += h2[(sp + 1) * C_];
    }
    g_H8[(((size_t)b * H_ + t) * H8_W + u) * C_ + c] = sum;
}

__global__ void __launch_bounds__(64) kB(
    const float* __restrict__ x,    const float* __restrict__ olsw,
    const float* __restrict__ anch, const float* __restrict__ wdth,
    const float* __restrict__ gmm,  const float* __restrict__ bta,
    const float* __restrict__ mea,  const float* __restrict__ vrr,
    float* __restrict__ out)
{
    const int c = threadIdx.x;
    const int j = blockIdx.x;
    const int i0 = blockIdx.y * CH_;
    const int b = blockIdx.z;

    // OLS slope coefficients: alpha = sum_r (w_r*dx_r/den) * ly_r
    const float w0 = olsw[0], w1 = olsw[1], w2 = olsw[2], w3 = olsw[3];
    const float L1 = 0.69314718f, L2 = 1.38629436f, L3 = 2.07944154f, L4 = 2.77258872f;
    const float wsum = w0 + w1 + w2 + w3;
    const float lrb = (w0 * L1 + w1 * L2 + w2 * L3 + w3 * L4) / wsum;
    const float d0 = L1 - lrb, d1 = L2 - lrb, d2 = L3 - lrb, d3 = L4 - lrb;
    const float den = w0 * d0 * d0 + w1 * d1 * d1 + w2 * d2 * d2 + w3 * d3 * d3;
    const float ivd = 1.f / den;
    const float c0 = w0 * d0 * ivd, c1 = w1 * d1 * ivd, c2 = w2 * d2 * ivd, c3 = w3 * d3 * ivd;

    const float bsc = gmm[c] * rsqrtf(vrr[c] + 1e-3f);
    const float bsh = bta[c] - mea[c] * bsc;

    float an[K_], wd[K_];
    #pragma unroll
    for (int k = 0; k < K_; k++) { an[k] = anch[c * K_ + k]; wd[k] = wdth[c * K_ + k]; }

    const size_t bh2 = (size_t)b * H_ * ST2;
    const size_t bh8 = (size_t)b * H_ * ST8;
    const float* p2   = g_H2 + bh2 + (j + 1) * C_ + c;   // h2 row t at +t*ST2
    const float* p4a  = g_H2 + bh2 + (j    ) * C_ + c;   // s = j-1
    const float* p4b  = g_H2 + bh2 + (j + 2) * C_ + c;   // s = j+1
    const float* p8   = g_H8 + bh8 + (j + 4) * C_ + c;   // s = j-3
    const float* p16a = g_H8 + bh8 + (j    ) * C_ + c;   // s = j-7
    const float* p16b = g_H8 + bh8 + (j + 8) * C_ + c;   // s = j+1
    const float* xr   = x   + ((size_t)b * H_ * W_ + j) * C_ + c;
    float*       orr  = out + ((size_t)b * H_ * W_ + j) * C_ + c;

    float r2[2], r4[4], r8[8], r16[16];

    // prefill rows i0-7 .. i0+7 (counter-aligned slots)
    #pragma unroll
    for (int d = -7; d <= 7; d++) {
        const int t = i0 + d;
        const bool v = (t >= 0);              // t < H_ guaranteed (t <= 175)
        r16[d + 7] = v ? (p16a[t * ST8] + p16b[t * ST8]) : 0.f;
        if (d >= -3 && d <= 3) r8[d + 3] = v ? p8[t * ST8] : 0.f;
        if (d >= -1 && d <= 1) r4[d + 1] = v ? (p4a[t * ST2] + p4b[t * ST2]) : 0.f;
        if (d == 0)            r2[0]     = v ? p2[t * ST2] : 0.f;
    }

    for (int base = 0; base < CH_; base += 16) {
        #pragma unroll
        for (int u = 0; u < 16; u++) {
            if (base + u >= CH_) break;
            const int i = i0 + base + u;
            const int t16 = i + 8, t8 = i + 4, t4 = i + 2, t2 = i + 1;
            // compile-time ring slots (base is a multiple of 16)
            r16[(15 + u) & 15] = (t16 < H_) ? (p16a[t16 * ST8] + p16b[t16 * ST8]) : 0.f;
            r8 [(7 + u) & 7]   = (t8  < H_) ? p8[t8 * ST8] : 0.f;
            r4 [(3 + u) & 3]   = (t4  < H_) ? (p4a[t4 * ST2] + p4b[t4 * ST2]) : 0.f;
            r2 [(1 + u) & 1]   = (t2  < H_) ? p2[t2 * ST2] : 0.f;

            const float m2 = r2[0] + r2[1];
            const float m4 = (r4[0] + r4[1]) + (r4[2] + r4[3]);
            const float m8 = ((r8[0] + r8[1]) + (r8[2] + r8[3]))
                           + ((r8[4] + r8[5]) + (r8[6] + r8[7]));
            const float m16 = (((r16[0] + r16[1]) + (r16[2] + r16[3]))
                            +  ((r16[4] + r16[5]) + (r16[6] + r16[7])))
                            + (((r16[8] + r16[9]) + (r16[10] + r16[11]))
                            +  ((r16[12] + r16[13]) + (r16[14] + r16[15])));

            const float ly0 = __logf(m2 + EPS_);
            const float ly1 = __logf(m4 + EPS_);
            const float ly2 = __logf(m8 + EPS_);
            const float ly3 = __logf(m16 + EPS_);
            const float alpha = fmaf(c3, ly3, fmaf(c2, ly2, fmaf(c1, ly1, c0 * ly0)));
            const float a = fmaf(alpha, bsc, bsh);

            float cnt = 0.f;
            #pragma unroll
            for (int k = 0; k < K_; k++) {
                float h = fmaf(-wd[k], fabsf(a - an[k]), 1.f);
                cnt += fmaxf(h, 0.f);
            }
            const float sig = __fdividef(1.f, 1.f + __expf(-cnt));
            orr[i * STX] = xr[i * STX] + sig;
        }
    }
}

extern "C" void kernel_launch(void* const* d_in, const int* in_sizes, int n_in,
                              void* d_out, int out_size) {
    const float* x    = (const float*)d_in[0];
    const float* olsw = (const float*)d_in[1];
    const float* anch = (const float*)d_in[2];
    const float* wdth = (const float*)d_in[3];
    const float* gmm  = (const float*)d_in[4];
    const float* bta  = (const float*)d_in[5];
    const float* mea  = (const float*)d_in[6];
    const float* vrr  = (const float*)d_in[7];
    float* out = (float*)d_out;

    k_init<<<1, 32>>>();
    k_minmax<<<dim3(120, B_), 256>>>(x);
    kA1<<<dim3((H2_W + 3) / 4, H_, B_), dim3(C_, 4)>>>(x);
    kA2<<<dim3((H8_W + 3) / 4, H_, B_), dim3(C_, 4)>>>();
    kB<<<dim3(W_, H_ / CH_, B_), C_>>>(x, olsw, anch, wdth, gmm, bta, mea, vrr, out);
}